// round 1
// baseline (speedup 1.0000x reference)
#include <cuda_runtime.h>
#include <math.h>

// ---------------------------------------------------------------------------
// BEV Multi-Scale Deformable Attention, GB300
// Strategy: projection commutes with bilinear sampling (both linear in C).
//   proj_l = Wk_l @ feat_l  (per pixel, 128 out-ch)   -- 3 small GEMM kernels
//   then one fused kernel per 8-query block:
//     off = q @ W_off^T + b_off
//     k(h,l,p) = bilinear_sample(proj_l, loc)[h*16:h*16+16] + bk_l[h*16:..]
//     logits -> softmax(0.25*logits over 12) -> weighted sum -> @W_out^T + b_out
// ---------------------------------------------------------------------------

#define N_HEADS   8
#define N_LEVELS  3
#define N_POINTS  4
#define D_MODEL   128
#define D_HEAD    16
#define LQ        6400

// level geometry (fixed by setup_inputs)
#define H0 128
#define W0 128
#define H1 64
#define W1 64
#define H2 32
#define W2 32
#define HW0 (H0*W0)
#define HW1 (H1*W1)
#define HW2 (H2*W2)

// scratch: projected key features, [pixel][128] row-major per level
__device__ float g_proj0[HW0 * 128];   // 8 MB
__device__ float g_proj1[HW1 * 128];   // 2 MB
__device__ float g_proj2[HW2 * 128];   // 0.5 MB

// ---------------------------------------------------------------------------
// Projection kernel: out[(base+px)*128 + tid] = sum_c Wk[tid*C+c]*feat[c*HW+base+px]
// block: 128 threads (one per output channel), PIX=32 pixels per block.
// ---------------------------------------------------------------------------
template <int C>
__global__ void proj_kernel(const float* __restrict__ feat,
                            const float* __restrict__ Wk,
                            float* __restrict__ out, int HW) {
    constexpr int PIX = 32;
    __shared__ float s[C * PIX];
    const int base = blockIdx.x * PIX;
    const int tid = threadIdx.x;  // 0..127

    // coalesced load of feature tile [C][PIX]
    for (int i = tid; i < C * PIX; i += 128) {
        int c = i / PIX, px = i % PIX;
        s[i] = feat[c * HW + base + px];
    }
    __syncthreads();

    float acc[PIX];
#pragma unroll
    for (int px = 0; px < PIX; px++) acc[px] = 0.f;

    const float* wrow = Wk + tid * C;
#pragma unroll 4
    for (int c = 0; c < C; c++) {
        float w = __ldg(wrow + c);
        const float4* s4 = reinterpret_cast<const float4*>(&s[c * PIX]);
#pragma unroll
        for (int v = 0; v < PIX / 4; v++) {
            float4 sv = s4[v];
            acc[v * 4 + 0] += w * sv.x;
            acc[v * 4 + 1] += w * sv.y;
            acc[v * 4 + 2] += w * sv.z;
            acc[v * 4 + 3] += w * sv.w;
        }
    }
#pragma unroll
    for (int px = 0; px < PIX; px++)
        out[(base + px) * 128 + tid] = acc[px];
}

// ---------------------------------------------------------------------------
// Fused attention kernel. QB queries per block, 256 threads.
// ---------------------------------------------------------------------------
#define QB 8
#define THREADS 256
#define NSAMP (N_HEADS * N_LEVELS * N_POINTS)   // 96
#define LPP   (N_LEVELS * N_POINTS)             // 12

// smem layout (floats)
#define SM_QS    0                         // QB*128      = 1024
#define SM_REF   (SM_QS + QB*128)          // QB*6        = 48
#define SM_OFF   (SM_REF + QB*8)           // QB*192      = 1536 (ref padded to 8)
#define SM_KS    (SM_OFF + QB*192)         // QB*96*16    = 12288
#define SM_LG    (SM_KS + QB*NSAMP*16)     // QB*96       = 768
#define SM_HS    (SM_LG + QB*NSAMP)        // QB*128      = 1024
#define SM_TOTAL (SM_HS + QB*128)
#define SMEM_BYTES (SM_TOTAL * sizeof(float))

__global__ __launch_bounds__(THREADS)
void msda_main_kernel(const float* __restrict__ query,
                      const float* __restrict__ refp,
                      const float* __restrict__ Woff,
                      const float* __restrict__ boff,
                      const float* __restrict__ bk0,
                      const float* __restrict__ bk1,
                      const float* __restrict__ bk2,
                      const float* __restrict__ Wout,
                      const float* __restrict__ bout,
                      float* __restrict__ out) {
    extern __shared__ float sm[];
    const int tid = threadIdx.x;
    const int qbase = blockIdx.x * QB;

    // ---- Phase A: load queries + reference points -------------------------
    for (int i = tid; i < QB * 128; i += THREADS)
        sm[SM_QS + i] = query[qbase * 128 + i];
    for (int i = tid; i < QB * 6; i += THREADS) {
        int q = i / 6, r = i % 6;
        sm[SM_REF + q * 8 + r] = refp[(qbase + q) * 6 + r];
    }
    __syncthreads();

    // ---- Phase B: offsets: off[q][j] = q_row . Woff[j] + boff[j] ----------
    if (tid < 192) {
        float acc[QB];
#pragma unroll
        for (int q = 0; q < QB; q++) acc[q] = 0.f;
        const float4* wr = reinterpret_cast<const float4*>(Woff + tid * 128);
#pragma unroll 4
        for (int c4 = 0; c4 < 32; c4++) {
            float4 w = __ldg(wr + c4);
#pragma unroll
            for (int q = 0; q < QB; q++) {
                const float4 qv = *reinterpret_cast<const float4*>(&sm[SM_QS + q * 128 + c4 * 4]);
                acc[q] += w.x * qv.x + w.y * qv.y + w.z * qv.z + w.w * qv.w;
            }
        }
        float b = __ldg(boff + tid);
#pragma unroll
        for (int q = 0; q < QB; q++)
            sm[SM_OFF + q * 192 + tid] = acc[q] + b;
    }
    __syncthreads();

    // ---- Phase C: bilinear sample projected keys + logits -----------------
    for (int i = tid; i < QB * NSAMP; i += THREADS) {
        const int q = i / NSAMP;
        const int s = i % NSAMP;
        const int h = s / LPP;
        const int lp = s % LPP;
        const int l = lp / N_POINTS;
        const int p = lp % N_POINTS;

        const float* proj;
        const float* bk;
        int Wl, Hl;
        float invW, invH;
        if (l == 0)      { proj = g_proj0; bk = bk0; Wl = W0; Hl = H0; invW = 1.f / W0; invH = 1.f / H0; }
        else if (l == 1) { proj = g_proj1; bk = bk1; Wl = W1; Hl = H1; invW = 1.f / W1; invH = 1.f / H1; }
        else             { proj = g_proj2; bk = bk2; Wl = W2; Hl = H2; invW = 1.f / W2; invH = 1.f / H2; }

        const int j = ((h * N_LEVELS + l) * N_POINTS + p) * 2;
        const float ox = sm[SM_OFF + q * 192 + j];
        const float oy = sm[SM_OFF + q * 192 + j + 1];
        const float rx = sm[SM_REF + q * 8 + l * 2];
        const float ry = sm[SM_REF + q * 8 + l * 2 + 1];
        const float locx = rx + ox * invW;
        const float locy = ry + oy * invH;

        const float x = locx * (float)Wl - 0.5f;
        const float y = locy * (float)Hl - 0.5f;
        const float xf = floorf(x), yf = floorf(y);
        const int x0 = (int)xf, y0 = (int)yf;
        const float wx = x - xf, wy = y - yf;

        float4 k0 = {0,0,0,0}, k1 = {0,0,0,0}, k2 = {0,0,0,0}, k3 = {0,0,0,0};

        const int hoff = h * D_HEAD;
#pragma unroll
        for (int t = 0; t < 4; t++) {
            const int xi = x0 + (t & 1);
            const int yi = y0 + (t >> 1);
            float w = ((t & 1) ? wx : (1.f - wx)) * ((t >> 1) ? wy : (1.f - wy));
            if (xi >= 0 && xi < Wl && yi >= 0 && yi < Hl) {
                const float4* pp = reinterpret_cast<const float4*>(proj + (yi * Wl + xi) * 128 + hoff);
                float4 v0 = __ldg(pp + 0), v1 = __ldg(pp + 1), v2 = __ldg(pp + 2), v3 = __ldg(pp + 3);
                k0.x += w * v0.x; k0.y += w * v0.y; k0.z += w * v0.z; k0.w += w * v0.w;
                k1.x += w * v1.x; k1.y += w * v1.y; k1.z += w * v1.z; k1.w += w * v1.w;
                k2.x += w * v2.x; k2.y += w * v2.y; k2.z += w * v2.z; k2.w += w * v2.w;
                k3.x += w * v3.x; k3.y += w * v3.y; k3.z += w * v3.z; k3.w += w * v3.w;
            }
        }
        // + bias (added unconditionally, matching reference)
        const float4* b4 = reinterpret_cast<const float4*>(bk + hoff);
        float4 bb0 = __ldg(b4 + 0), bb1 = __ldg(b4 + 1), bb2 = __ldg(b4 + 2), bb3 = __ldg(b4 + 3);
        k0.x += bb0.x; k0.y += bb0.y; k0.z += bb0.z; k0.w += bb0.w;
        k1.x += bb1.x; k1.y += bb1.y; k1.z += bb1.z; k1.w += bb1.w;
        k2.x += bb2.x; k2.y += bb2.y; k2.z += bb2.z; k2.w += bb2.w;
        k3.x += bb3.x; k3.y += bb3.y; k3.z += bb3.z; k3.w += bb3.w;

        // logit = qh . k
        const float4* qv = reinterpret_cast<const float4*>(&sm[SM_QS + q * 128 + hoff]);
        float4 q0 = qv[0], q1 = qv[1], q2 = qv[2], q3 = qv[3];
        float lg = q0.x * k0.x + q0.y * k0.y + q0.z * k0.z + q0.w * k0.w
                 + q1.x * k1.x + q1.y * k1.y + q1.z * k1.z + q1.w * k1.w
                 + q2.x * k2.x + q2.y * k2.y + q2.z * k2.z + q2.w * k2.w
                 + q3.x * k3.x + q3.y * k3.y + q3.z * k3.z + q3.w * k3.w;

        float4* kdst = reinterpret_cast<float4*>(&sm[SM_KS + (q * NSAMP + s) * D_HEAD]);
        kdst[0] = k0; kdst[1] = k1; kdst[2] = k2; kdst[3] = k3;
        sm[SM_LG + q * NSAMP + s] = lg;
    }
    __syncthreads();

    // ---- Phase D: softmax per (q, h) over 12 -------------------------------
    if (tid < QB * N_HEADS) {
        const int q = tid / N_HEADS, h = tid % N_HEADS;
        float* lrow = &sm[SM_LG + q * NSAMP + h * LPP];
        float m = -1e30f;
#pragma unroll
        for (int t = 0; t < LPP; t++) m = fmaxf(m, 0.25f * lrow[t]);
        float ssum = 0.f;
#pragma unroll
        for (int t = 0; t < LPP; t++) {
            float e = __expf(0.25f * lrow[t] - m);
            lrow[t] = e;
            ssum += e;
        }
        float inv = 1.f / ssum;
#pragma unroll
        for (int t = 0; t < LPP; t++) lrow[t] *= inv;
    }
    __syncthreads();

    // ---- Phase E: weighted sum -> head-concat vector ------------------------
    for (int i = tid; i < QB * 128; i += THREADS) {
        const int q = i / 128;
        const int hd = i % 128;
        const int h = hd / D_HEAD;
        const int d = hd % D_HEAD;
        float a = 0.f;
        const float* attn = &sm[SM_LG + q * NSAMP + h * LPP];
        const float* kk = &sm[SM_KS + (q * NSAMP + h * LPP) * D_HEAD + d];
#pragma unroll
        for (int lp = 0; lp < LPP; lp++)
            a += attn[lp] * kk[lp * D_HEAD];
        sm[SM_HS + i] = a;
    }
    __syncthreads();

    // ---- Phase F: output projection: out = hs @ Wout^T + bout --------------
    {
        const int o = tid & 127;
        const int half = tid >> 7;            // 0 or 1, 4 queries each
        float acc[QB / 2];
#pragma unroll
        for (int t = 0; t < QB / 2; t++) acc[t] = 0.f;
        const float4* wr = reinterpret_cast<const float4*>(Wout + o * 128);
#pragma unroll 4
        for (int c4 = 0; c4 < 32; c4++) {
            float4 w = __ldg(wr + c4);
#pragma unroll
            for (int t = 0; t < QB / 2; t++) {
                const int q = half * (QB / 2) + t;
                const float4 hv = *reinterpret_cast<const float4*>(&sm[SM_HS + q * 128 + c4 * 4]);
                acc[t] += w.x * hv.x + w.y * hv.y + w.z * hv.z + w.w * hv.w;
            }
        }
        const float b = __ldg(bout + o);
#pragma unroll
        for (int t = 0; t < QB / 2; t++) {
            const int q = half * (QB / 2) + t;
            out[(qbase + q) * 128 + o] = acc[t] + b;
        }
    }
}

// ---------------------------------------------------------------------------
// Launch
// ---------------------------------------------------------------------------
extern "C" void kernel_launch(void* const* d_in, const int* in_sizes, int n_in,
                              void* d_out, int out_size) {
    const float* query = (const float*)d_in[0];
    const float* refp  = (const float*)d_in[1];
    const float* feat0 = (const float*)d_in[2];
    const float* feat1 = (const float*)d_in[3];
    const float* feat2 = (const float*)d_in[4];
    // d_in[5] = input_spatial_shapes (compile-time constants here)
    const float* Woff  = (const float*)d_in[6];
    const float* boff  = (const float*)d_in[7];
    const float* Wk0   = (const float*)d_in[8];
    const float* bk0   = (const float*)d_in[9];
    const float* Wk1   = (const float*)d_in[10];
    const float* bk1   = (const float*)d_in[11];
    const float* Wk2   = (const float*)d_in[12];
    const float* bk2   = (const float*)d_in[13];
    const float* Wout  = (const float*)d_in[14];
    const float* bout  = (const float*)d_in[15];
    float* out = (float*)d_out;

    float *p0, *p1, *p2;
    cudaGetSymbolAddress((void**)&p0, g_proj0);
    cudaGetSymbolAddress((void**)&p1, g_proj1);
    cudaGetSymbolAddress((void**)&p2, g_proj2);

    proj_kernel<128><<<HW0 / 32, 128>>>(feat0, Wk0, p0, HW0);
    proj_kernel<128><<<HW1 / 32, 128>>>(feat1, Wk1, p1, HW1);
    proj_kernel<64><<<HW2 / 32, 128>>>(feat2, Wk2, p2, HW2);

    static bool attr_set = false;
    if (!attr_set) {
        cudaFuncSetAttribute(msda_main_kernel,
                             cudaFuncAttributeMaxDynamicSharedMemorySize,
                             (int)SMEM_BYTES);
        attr_set = true;
    }
    msda_main_kernel<<<LQ / QB, THREADS, SMEM_BYTES>>>(
        query, refp, Woff, boff, bk0, bk1, bk2, Wout, bout, out);
}

// round 2
// speedup vs baseline: 1.7334x; 1.7334x over previous
#include <cuda_runtime.h>
#include <math.h>

#define N_HEADS   8
#define N_LEVELS  3
#define N_POINTS  4
#define D_MODEL   128
#define D_HEAD    16
#define LQ        6400

#define H0 128
#define W0 128
#define H1 64
#define W1 64
#define H2 32
#define W2 32
#define HW0 (H0*W0)
#define HW1 (H1*W1)
#define HW2 (H2*W2)

// scratch: projected key features [pixel][128] per level, + transposed weights
__device__ float g_proj0[HW0 * 128];
__device__ float g_proj1[HW1 * 128];
__device__ float g_proj2[HW2 * 128];
__device__ float g_wofft[128 * 192];   // WoffT[c][j]
__device__ float g_woutt[128 * 128];   // WoutT[c][o]

// ---------------------------------------------------------------------------
// packed f32x2 fma helper
// ---------------------------------------------------------------------------
__device__ __forceinline__ void ffma2(unsigned long long& acc,
                                      unsigned long long a,
                                      unsigned long long b) {
    asm("fma.rn.f32x2 %0, %1, %2, %0;" : "+l"(acc) : "l"(a), "l"(b));
}
__device__ __forceinline__ unsigned long long bcast2(float w) {
    unsigned int wb = __float_as_uint(w);
    return ((unsigned long long)wb << 32) | wb;
}
__device__ __forceinline__ float lo2(unsigned long long v) {
    return __uint_as_float((unsigned int)v);
}
__device__ __forceinline__ float hi2(unsigned long long v) {
    return __uint_as_float((unsigned int)(v >> 32));
}

// ---------------------------------------------------------------------------
// Combined transpose: blocks 0..23 -> Woff (192x128 -> 128x192),
//                     blocks 24..39 -> Wout (128x128 -> 128x128)
// block: (32, 8)
// ---------------------------------------------------------------------------
__global__ void transpose_kernel(const float* __restrict__ Woff,
                                 const float* __restrict__ Wout,
                                 float* __restrict__ WoffT,
                                 float* __restrict__ WoutT) {
    __shared__ float t[32][33];
    const float* in;
    float* out;
    int rows, cols, bx, by;
    int b = blockIdx.x;
    if (b < 24) {            // Woff: rows=192, cols=128 -> tiles 6 (row) x 4 (col)
        in = Woff; out = WoffT; rows = 192; cols = 128;
        by = (b / 4) * 32; bx = (b % 4) * 32;
    } else {                 // Wout: 128x128 -> 4x4 tiles
        b -= 24;
        in = Wout; out = WoutT; rows = 128; cols = 128;
        by = (b / 4) * 32; bx = (b % 4) * 32;
    }
    int x = bx + threadIdx.x;
#pragma unroll
    for (int dy = 0; dy < 32; dy += 8) {
        int y = by + threadIdx.y + dy;
        if (y < rows && x < cols)
            t[threadIdx.y + dy][threadIdx.x] = in[y * cols + x];
    }
    __syncthreads();
    int xo = by + threadIdx.x;           // output col = original row
#pragma unroll
    for (int dy = 0; dy < 32; dy += 8) {
        int yo = bx + threadIdx.y + dy;  // output row = original col
        if (yo < cols && xo < rows)
            out[yo * rows + xo] = t[threadIdx.x][threadIdx.y + dy];
    }
}

// ---------------------------------------------------------------------------
// Projection: out[(base+px)*128 + tid] = sum_c Wk[tid*C+c] * feat[c*HW+base+px]
// f32x2-packed over pixel pairs. 128 threads, 32 pixels per block.
// ---------------------------------------------------------------------------
template <int C>
__global__ void proj_kernel(const float* __restrict__ feat,
                            const float* __restrict__ Wk,
                            float* __restrict__ out, int HW) {
    constexpr int PIX = 32;
    __shared__ float s[C * PIX];
    const int base = blockIdx.x * PIX;
    const int tid = threadIdx.x;

    for (int i = tid; i < C * PIX; i += 128) {
        int c = i >> 5, px = i & 31;
        s[i] = feat[c * HW + base + px];
    }
    __syncthreads();

    unsigned long long acc[PIX / 2];
#pragma unroll
    for (int v = 0; v < PIX / 2; v++) acc[v] = 0ULL;

    const float4* wrow4 = reinterpret_cast<const float4*>(Wk + tid * C);
#pragma unroll 2
    for (int c4 = 0; c4 < C / 4; c4++) {
        float4 w4 = __ldg(wrow4 + c4);
        float wv[4] = {w4.x, w4.y, w4.z, w4.w};
#pragma unroll
        for (int u = 0; u < 4; u++) {
            unsigned long long ww = bcast2(wv[u]);
            const unsigned long long* s2 =
                reinterpret_cast<const unsigned long long*>(&s[(c4 * 4 + u) * PIX]);
#pragma unroll
            for (int v = 0; v < PIX / 2; v++)
                ffma2(acc[v], ww, s2[v]);
        }
    }
#pragma unroll
    for (int v = 0; v < PIX / 2; v++) {
        out[(base + 2 * v) * 128 + tid]     = lo2(acc[v]);
        out[(base + 2 * v + 1) * 128 + tid] = hi2(acc[v]);
    }
}

// ---------------------------------------------------------------------------
// Fused attention kernel. QB queries / block, 256 threads.
// ---------------------------------------------------------------------------
#define QB 8
#define THREADS 256
#define NSAMP (N_HEADS * N_LEVELS * N_POINTS)   // 96
#define LPP   (N_LEVELS * N_POINTS)             // 12

// smem layout (float indices)
#define SM_QS    0                           // [q][c]      1024
#define SM_QT    (SM_QS + QB*128)            // [c][q]      1024 (f32x2 pairs)
#define SM_REF   (SM_QT + 128*QB)            // [q][8]      64
#define SM_OFF   (SM_REF + QB*8)             // [q][192]    1536
#define SM_KS    (SM_OFF + QB*192)           // [q][s][16]  12288
#define SM_LG    (SM_KS + QB*NSAMP*16)       // [q][s]      768
#define SM_HT    (SM_LG + QB*NSAMP)          // [c][q]      1024 (f32x2 pairs)
#define SM_TOTAL (SM_HT + 128*QB)
#define SMEM_BYTES (SM_TOTAL * sizeof(float))

__global__ __launch_bounds__(THREADS)
void msda_main_kernel(const float* __restrict__ query,
                      const float* __restrict__ refp,
                      const float* __restrict__ WoffT,
                      const float* __restrict__ boff,
                      const float* __restrict__ bk0,
                      const float* __restrict__ bk1,
                      const float* __restrict__ bk2,
                      const float* __restrict__ WoutT,
                      const float* __restrict__ bout,
                      float* __restrict__ out) {
    extern __shared__ float sm[];
    const int tid = threadIdx.x;
    const int qbase = blockIdx.x * QB;

    // ---- Phase A: queries (both layouts) + reference points ----------------
    for (int i = tid; i < QB * 128; i += THREADS) {
        float v = query[qbase * 128 + i];
        sm[SM_QS + i] = v;
        int q = i >> 7, c = i & 127;
        sm[SM_QT + c * QB + q] = v;
    }
    for (int i = tid; i < QB * 6; i += THREADS) {
        int q = i / 6, r = i % 6;
        sm[SM_REF + q * 8 + r] = refp[(qbase + q) * 6 + r];
    }
    __syncthreads();

    // ---- Phase B: offsets off[q][j] = q . WoffT[:,j] + boff[j] -------------
    if (tid < 192) {
        unsigned long long acc[QB / 2] = {0, 0, 0, 0};
        const float* wt = WoffT + tid;
#pragma unroll 4
        for (int c = 0; c < 128; c++) {
            unsigned long long ww = bcast2(__ldg(wt + c * 192));
            const unsigned long long* qp =
                reinterpret_cast<const unsigned long long*>(&sm[SM_QT + c * QB]);
#pragma unroll
            for (int k = 0; k < QB / 2; k++)
                ffma2(acc[k], ww, qp[k]);
        }
        float b = __ldg(boff + tid);
#pragma unroll
        for (int k = 0; k < QB / 2; k++) {
            sm[SM_OFF + (2 * k) * 192 + tid]     = lo2(acc[k]) + b;
            sm[SM_OFF + (2 * k + 1) * 192 + tid] = hi2(acc[k]) + b;
        }
    }
    __syncthreads();

    // ---- Phase C: quad-cooperative bilinear gather + logits ----------------
    // 4 lanes per sample; lane d4 owns key dims [d4*4, d4*4+4)
    for (int i = tid; i < QB * NSAMP * 4; i += THREADS) {
        const int d4 = i & 3;
        const int quad = i >> 2;
        const int q = quad / NSAMP;
        const int s = quad - q * NSAMP;
        const int h = s / LPP;
        const int lp = s - h * LPP;
        const int l = lp >> 2;
        const int p = lp & 3;

        const float* proj;
        const float* bk;
        int Wl, Hl;
        float invW, invH;
        if (l == 0)      { proj = g_proj0; bk = bk0; Wl = W0; Hl = H0; invW = 1.f / W0; invH = 1.f / H0; }
        else if (l == 1) { proj = g_proj1; bk = bk1; Wl = W1; Hl = H1; invW = 1.f / W1; invH = 1.f / H1; }
        else             { proj = g_proj2; bk = bk2; Wl = W2; Hl = H2; invW = 1.f / W2; invH = 1.f / H2; }

        const int j2 = ((h * N_LEVELS + l) * N_POINTS + p) * 2;
        const float ox = sm[SM_OFF + q * 192 + j2];
        const float oy = sm[SM_OFF + q * 192 + j2 + 1];
        const float rx = sm[SM_REF + q * 8 + l * 2];
        const float ry = sm[SM_REF + q * 8 + l * 2 + 1];
        const float locx = rx + ox * invW;
        const float locy = ry + oy * invH;

        const float x = locx * (float)Wl - 0.5f;
        const float y = locy * (float)Hl - 0.5f;
        const float xf = floorf(x), yf = floorf(y);
        const int x0 = (int)xf, y0 = (int)yf;
        const float wx = x - xf, wy = y - yf;

        const int coff = h * D_HEAD + d4 * 4;
        const float* projc = proj + coff;

        float4 k = {0.f, 0.f, 0.f, 0.f};
#pragma unroll
        for (int t = 0; t < 4; t++) {
            const int xi = x0 + (t & 1);
            const int yi = y0 + (t >> 1);
            const float w = ((t & 1) ? wx : (1.f - wx)) * ((t >> 1) ? wy : (1.f - wy));
            if (xi >= 0 && xi < Wl && yi >= 0 && yi < Hl) {
                float4 v = __ldg(reinterpret_cast<const float4*>(projc + (yi * Wl + xi) * 128));
                k.x += w * v.x; k.y += w * v.y; k.z += w * v.z; k.w += w * v.w;
            }
        }
        float4 bb = __ldg(reinterpret_cast<const float4*>(bk + coff));
        k.x += bb.x; k.y += bb.y; k.z += bb.z; k.w += bb.w;

        // partial logit over this lane's 4 dims, reduce within quad
        float4 qv = *reinterpret_cast<const float4*>(&sm[SM_QS + q * 128 + coff]);
        float part = qv.x * k.x + qv.y * k.y + qv.z * k.z + qv.w * k.w;
        part += __shfl_xor_sync(0xffffffffu, part, 1);
        part += __shfl_xor_sync(0xffffffffu, part, 2);

        *reinterpret_cast<float4*>(&sm[SM_KS + (q * NSAMP + s) * D_HEAD + d4 * 4]) = k;
        if (d4 == 0) sm[SM_LG + q * NSAMP + s] = part;
    }
    __syncthreads();

    // ---- Phase D: softmax per (q, h) over 12 -------------------------------
    if (tid < QB * N_HEADS) {
        const int q = tid / N_HEADS, h = tid % N_HEADS;
        float* lrow = &sm[SM_LG + q * NSAMP + h * LPP];
        float m = -1e30f;
#pragma unroll
        for (int t = 0; t < LPP; t++) m = fmaxf(m, 0.25f * lrow[t]);
        float ssum = 0.f;
#pragma unroll
        for (int t = 0; t < LPP; t++) {
            float e = __expf(0.25f * lrow[t] - m);
            lrow[t] = e;
            ssum += e;
        }
        float inv = 1.f / ssum;
#pragma unroll
        for (int t = 0; t < LPP; t++) lrow[t] *= inv;
    }
    __syncthreads();

    // ---- Phase E: weighted sum -> transposed hidden [c][q] ------------------
    for (int i = tid; i < QB * 128; i += THREADS) {
        const int q = i >> 7;
        const int hd = i & 127;
        const int h = hd / D_HEAD;
        const int d = hd % D_HEAD;
        float a = 0.f;
        const float* attn = &sm[SM_LG + q * NSAMP + h * LPP];
        const float* kk = &sm[SM_KS + (q * NSAMP + h * LPP) * D_HEAD + d];
#pragma unroll
        for (int lp = 0; lp < LPP; lp++)
            a += attn[lp] * kk[lp * D_HEAD];
        sm[SM_HT + hd * QB + q] = a;
    }
    __syncthreads();

    // ---- Phase F: output projection out[q][o] = hs[q] . WoutT[:,o] + b -----
    {
        const int o = tid & 127;
        const int half = tid >> 7;   // 0 -> q 0..3, 1 -> q 4..7
        unsigned long long acc[2] = {0, 0};
        const float* wt = WoutT + o;
#pragma unroll 4
        for (int c = 0; c < 128; c++) {
            unsigned long long ww = bcast2(__ldg(wt + c * 128));
            const unsigned long long* hp =
                reinterpret_cast<const unsigned long long*>(&sm[SM_HT + c * QB + half * 4]);
            ffma2(acc[0], ww, hp[0]);
            ffma2(acc[1], ww, hp[1]);
        }
        const float b = __ldg(bout + o);
#pragma unroll
        for (int k = 0; k < 2; k++) {
            const int q = half * 4 + 2 * k;
            out[(qbase + q) * 128 + o]     = lo2(acc[k]) + b;
            out[(qbase + q + 1) * 128 + o] = hi2(acc[k]) + b;
        }
    }
}

// ---------------------------------------------------------------------------
// Launch
// ---------------------------------------------------------------------------
extern "C" void kernel_launch(void* const* d_in, const int* in_sizes, int n_in,
                              void* d_out, int out_size) {
    const float* query = (const float*)d_in[0];
    const float* refp  = (const float*)d_in[1];
    const float* feat0 = (const float*)d_in[2];
    const float* feat1 = (const float*)d_in[3];
    const float* feat2 = (const float*)d_in[4];
    const float* Woff  = (const float*)d_in[6];
    const float* boff  = (const float*)d_in[7];
    const float* Wk0   = (const float*)d_in[8];
    const float* bk0   = (const float*)d_in[9];
    const float* Wk1   = (const float*)d_in[10];
    const float* bk1   = (const float*)d_in[11];
    const float* Wk2   = (const float*)d_in[12];
    const float* bk2   = (const float*)d_in[13];
    const float* Wout  = (const float*)d_in[14];
    const float* bout  = (const float*)d_in[15];
    float* out = (float*)d_out;

    float *p0, *p1, *p2, *wofft, *woutt;
    cudaGetSymbolAddress((void**)&p0, g_proj0);
    cudaGetSymbolAddress((void**)&p1, g_proj1);
    cudaGetSymbolAddress((void**)&p2, g_proj2);
    cudaGetSymbolAddress((void**)&wofft, g_wofft);
    cudaGetSymbolAddress((void**)&woutt, g_woutt);

    transpose_kernel<<<40, dim3(32, 8)>>>(Woff, Wout, wofft, woutt);
    proj_kernel<128><<<HW0 / 32, 128>>>(feat0, Wk0, p0, HW0);
    proj_kernel<128><<<HW1 / 32, 128>>>(feat1, Wk1, p1, HW1);
    proj_kernel<64><<<HW2 / 32, 128>>>(feat2, Wk2, p2, HW2);

    static bool attr_set = false;
    if (!attr_set) {
        cudaFuncSetAttribute(msda_main_kernel,
                             cudaFuncAttributeMaxDynamicSharedMemorySize,
                             (int)SMEM_BYTES);
        attr_set = true;
    }
    msda_main_kernel<<<LQ / QB, THREADS, SMEM_BYTES>>>(
        query, refp, wofft, boff, bk0, bk1, bk2, woutt, bout, out);
}

// round 3
// speedup vs baseline: 1.9970x; 1.1521x over previous
#include <cuda_runtime.h>
#include <math.h>

#define N_HEADS   8
#define N_LEVELS  3
#define N_POINTS  4
#define D_MODEL   128
#define D_HEAD    16
#define LQ        6400

#define H0 128
#define W0 128
#define H1 64
#define W1 64
#define H2 32
#define W2 32
#define HW0 (H0*W0)
#define HW1 (H1*W1)
#define HW2 (H2*W2)

// scratch: projected key features [pixel][128] per level, + transposed weights
__device__ float g_proj0[HW0 * 128];
__device__ float g_proj1[HW1 * 128];
__device__ float g_proj2[HW2 * 128];
__device__ float g_wofft[128 * 192];   // WoffT[c][j]
__device__ float g_woutt[128 * 128];   // WoutT[c][o]

// ---------------------------------------------------------------------------
// packed f32x2 helpers
// ---------------------------------------------------------------------------
__device__ __forceinline__ void ffma2(unsigned long long& acc,
                                      unsigned long long a,
                                      unsigned long long b) {
    asm("fma.rn.f32x2 %0, %1, %2, %0;" : "+l"(acc) : "l"(a), "l"(b));
}
__device__ __forceinline__ unsigned long long bcast2(float w) {
    unsigned int wb = __float_as_uint(w);
    return ((unsigned long long)wb << 32) | wb;
}
__device__ __forceinline__ float lo2(unsigned long long v) {
    return __uint_as_float((unsigned int)v);
}
__device__ __forceinline__ float hi2(unsigned long long v) {
    return __uint_as_float((unsigned int)(v >> 32));
}

// ---------------------------------------------------------------------------
// prep kernel building blocks (all run with 128 threads)
// ---------------------------------------------------------------------------
template <int C>
__device__ void proj_block(const float* __restrict__ feat,
                           const float* __restrict__ Wk,
                           float* __restrict__ out, int HW, int blk,
                           float* s) {
    constexpr int PIX = 32;
    const int base = blk * PIX;
    const int tid = threadIdx.x;

    for (int i = tid; i < C * PIX; i += 128) {
        int c = i >> 5, px = i & 31;
        s[i] = feat[c * HW + base + px];
    }
    __syncthreads();

    unsigned long long acc[PIX / 2];
#pragma unroll
    for (int v = 0; v < PIX / 2; v++) acc[v] = 0ULL;

    const float4* wrow4 = reinterpret_cast<const float4*>(Wk + tid * C);
#pragma unroll 2
    for (int c4 = 0; c4 < C / 4; c4++) {
        float4 w4 = __ldg(wrow4 + c4);
        float wv[4] = {w4.x, w4.y, w4.z, w4.w};
#pragma unroll
        for (int u = 0; u < 4; u++) {
            unsigned long long ww = bcast2(wv[u]);
            const unsigned long long* s2 =
                reinterpret_cast<const unsigned long long*>(&s[(c4 * 4 + u) * PIX]);
#pragma unroll
            for (int v = 0; v < PIX / 2; v++)
                ffma2(acc[v], ww, s2[v]);
        }
    }
#pragma unroll
    for (int v = 0; v < PIX / 2; v++) {
        out[(base + 2 * v) * 128 + tid]     = lo2(acc[v]);
        out[(base + 2 * v + 1) * 128 + tid] = hi2(acc[v]);
    }
}

__device__ void transpose_block(int b,
                                const float* __restrict__ Woff,
                                const float* __restrict__ Wout,
                                float* __restrict__ WoffT,
                                float* __restrict__ WoutT,
                                float* tile /* >= 32*33 floats */) {
    const float* in;
    float* out;
    int rows, cols, bx, by;
    if (b < 24) {            // Woff: 192x128 -> 6x4 tiles of 32
        in = Woff; out = WoffT; rows = 192; cols = 128;
        by = (b / 4) * 32; bx = (b % 4) * 32;
    } else {                 // Wout: 128x128 -> 4x4 tiles
        b -= 24;
        in = Wout; out = WoutT; rows = 128; cols = 128;
        by = (b / 4) * 32; bx = (b % 4) * 32;
    }
    const int tx = threadIdx.x & 31;
    const int ty0 = threadIdx.x >> 5;        // 0..3
    const int x = bx + tx;
#pragma unroll
    for (int dy = ty0; dy < 32; dy += 4) {
        int y = by + dy;
        if (y < rows && x < cols) tile[dy * 33 + tx] = in[y * cols + x];
    }
    __syncthreads();
    const int xo = by + tx;
#pragma unroll
    for (int dy = ty0; dy < 32; dy += 4) {
        int yo = bx + dy;
        if (yo < cols && xo < rows) out[yo * rows + xo] = tile[tx * 33 + dy];
    }
}

// One fat kernel: 512 proj0 + 128 proj1 + 32 proj2 + 40 transpose blocks.
__global__ __launch_bounds__(128)
void prep_kernel(const float* __restrict__ feat0,
                 const float* __restrict__ feat1,
                 const float* __restrict__ feat2,
                 const float* __restrict__ Wk0,
                 const float* __restrict__ Wk1,
                 const float* __restrict__ Wk2,
                 const float* __restrict__ Woff,
                 const float* __restrict__ Wout) {
    __shared__ float s[128 * 32];   // 16 KB, reused by all variants
    const int b = blockIdx.x;
    if (b < 512) {
        proj_block<128>(feat0, Wk0, g_proj0, HW0, b, s);
    } else if (b < 640) {
        proj_block<128>(feat1, Wk1, g_proj1, HW1, b - 512, s);
    } else if (b < 672) {
        proj_block<64>(feat2, Wk2, g_proj2, HW2, b - 640, s);
    } else {
        transpose_block(b - 672, Woff, Wout, g_wofft, g_woutt, s);
    }
}

// ---------------------------------------------------------------------------
// Fused attention kernel. QB queries / block, 256 threads.
// ---------------------------------------------------------------------------
#define QB 8
#define THREADS 256
#define NSAMP (N_HEADS * N_LEVELS * N_POINTS)   // 96
#define LPP   (N_LEVELS * N_POINTS)             // 12

#define SM_QS    0                           // [q][c]      1024
#define SM_QT    (SM_QS + QB*128)            // [c][q]      1024
#define SM_REF   (SM_QT + 128*QB)            // [q][8]      64
#define SM_OFF   (SM_REF + QB*8)             // [q][192]    1536
#define SM_KS    (SM_OFF + QB*192)           // [q][s][16]  12288
#define SM_LG    (SM_KS + QB*NSAMP*16)       // [q][s]      768
#define SM_HT    (SM_LG + QB*NSAMP)          // [c][q]      1024
#define SM_TOTAL (SM_HT + 128*QB)
#define SMEM_BYTES (SM_TOTAL * sizeof(float))

__global__ __launch_bounds__(THREADS)
void msda_main_kernel(const float* __restrict__ query,
                      const float* __restrict__ refp,
                      const float* __restrict__ WoffT,
                      const float* __restrict__ boff,
                      const float* __restrict__ bk0,
                      const float* __restrict__ bk1,
                      const float* __restrict__ bk2,
                      const float* __restrict__ WoutT,
                      const float* __restrict__ bout,
                      float* __restrict__ out) {
    extern __shared__ float sm[];
    const int tid = threadIdx.x;
    const int qbase = blockIdx.x * QB;

    // ---- Phase A: queries (both layouts) + reference points ----------------
    for (int i = tid; i < QB * 128; i += THREADS) {
        float v = query[qbase * 128 + i];
        sm[SM_QS + i] = v;
        int q = i >> 7, c = i & 127;
        sm[SM_QT + c * QB + q] = v;
    }
    for (int i = tid; i < QB * 6; i += THREADS) {
        int q = i / 6, r = i % 6;
        sm[SM_REF + q * 8 + r] = refp[(qbase + q) * 6 + r];
    }
    __syncthreads();

    // ---- Phase B: offsets off[q][j] = q . WoffT[:,j] + boff[j] -------------
    if (tid < 192) {
        unsigned long long acc[QB / 2] = {0, 0, 0, 0};
        const float* wt = WoffT + tid;
#pragma unroll 4
        for (int c = 0; c < 128; c++) {
            unsigned long long ww = bcast2(__ldg(wt + c * 192));
            const unsigned long long* qp =
                reinterpret_cast<const unsigned long long*>(&sm[SM_QT + c * QB]);
#pragma unroll
            for (int k = 0; k < QB / 2; k++)
                ffma2(acc[k], ww, qp[k]);
        }
        float b = __ldg(boff + tid);
#pragma unroll
        for (int k = 0; k < QB / 2; k++) {
            sm[SM_OFF + (2 * k) * 192 + tid]     = lo2(acc[k]) + b;
            sm[SM_OFF + (2 * k + 1) * 192 + tid] = hi2(acc[k]) + b;
        }
    }
    __syncthreads();

    // ---- Phase C: quad-cooperative bilinear gather + logits ----------------
    // 4 lanes per sample; lane d4 owns key dims [d4*4, d4*4+4)
    // Branch-free: clamped indices, weight zeroed when out of bounds -> 4
    // independent LDG.128 batched for MLP.
    for (int i = tid; i < QB * NSAMP * 4; i += THREADS) {
        const int d4 = i & 3;
        const int quad = i >> 2;
        const int q = quad / NSAMP;
        const int s = quad - q * NSAMP;
        const int h = s / LPP;
        const int lp = s - h * LPP;
        const int l = lp >> 2;
        const int p = lp & 3;

        const float* proj;
        const float* bk;
        int Wl, Hl;
        float invW, invH;
        if (l == 0)      { proj = g_proj0; bk = bk0; Wl = W0; Hl = H0; invW = 1.f / W0; invH = 1.f / H0; }
        else if (l == 1) { proj = g_proj1; bk = bk1; Wl = W1; Hl = H1; invW = 1.f / W1; invH = 1.f / H1; }
        else             { proj = g_proj2; bk = bk2; Wl = W2; Hl = H2; invW = 1.f / W2; invH = 1.f / H2; }

        const int j2 = ((h * N_LEVELS + l) * N_POINTS + p) * 2;
        const float ox = sm[SM_OFF + q * 192 + j2];
        const float oy = sm[SM_OFF + q * 192 + j2 + 1];
        const float rx = sm[SM_REF + q * 8 + l * 2];
        const float ry = sm[SM_REF + q * 8 + l * 2 + 1];
        const float locx = rx + ox * invW;
        const float locy = ry + oy * invH;

        const float x = locx * (float)Wl - 0.5f;
        const float y = locy * (float)Hl - 0.5f;
        const float xf = floorf(x), yf = floorf(y);
        const int x0 = (int)xf, y0 = (int)yf;
        const float wx = x - xf, wy = y - yf;

        // per-corner weights (zeroed when OOB) + clamped addresses
        const int coff = h * D_HEAD + d4 * 4;
        const float* projc = proj + coff;

        float wgt[4];
        const float4* addr[4];
#pragma unroll
        for (int t = 0; t < 4; t++) {
            const int xi = x0 + (t & 1);
            const int yi = y0 + (t >> 1);
            const bool valid = (xi >= 0) & (xi < Wl) & (yi >= 0) & (yi < Hl);
            const float w = ((t & 1) ? wx : (1.f - wx)) * ((t >> 1) ? wy : (1.f - wy));
            wgt[t] = valid ? w : 0.f;
            const int xic = min(max(xi, 0), Wl - 1);
            const int yic = min(max(yi, 0), Hl - 1);
            addr[t] = reinterpret_cast<const float4*>(projc + (yic * Wl + xic) * 128);
        }
        float4 v0 = __ldg(addr[0]);
        float4 v1 = __ldg(addr[1]);
        float4 v2 = __ldg(addr[2]);
        float4 v3 = __ldg(addr[3]);

        float4 bb = __ldg(reinterpret_cast<const float4*>(bk + coff));
        float4 k;
        k.x = bb.x + wgt[0] * v0.x + wgt[1] * v1.x + wgt[2] * v2.x + wgt[3] * v3.x;
        k.y = bb.y + wgt[0] * v0.y + wgt[1] * v1.y + wgt[2] * v2.y + wgt[3] * v3.y;
        k.z = bb.z + wgt[0] * v0.z + wgt[1] * v1.z + wgt[2] * v2.z + wgt[3] * v3.z;
        k.w = bb.w + wgt[0] * v0.w + wgt[1] * v1.w + wgt[2] * v2.w + wgt[3] * v3.w;

        // partial logit over this lane's 4 dims, reduce within quad
        float4 qv = *reinterpret_cast<const float4*>(&sm[SM_QS + q * 128 + coff]);
        float part = qv.x * k.x + qv.y * k.y + qv.z * k.z + qv.w * k.w;
        part += __shfl_xor_sync(0xffffffffu, part, 1);
        part += __shfl_xor_sync(0xffffffffu, part, 2);

        *reinterpret_cast<float4*>(&sm[SM_KS + (q * NSAMP + s) * D_HEAD + d4 * 4]) = k;
        if (d4 == 0) sm[SM_LG + q * NSAMP + s] = part;
    }
    __syncthreads();

    // ---- Phase D: softmax per (q, h) over 12 -------------------------------
    if (tid < QB * N_HEADS) {
        const int q = tid / N_HEADS, h = tid % N_HEADS;
        float* lrow = &sm[SM_LG + q * NSAMP + h * LPP];
        float m = -1e30f;
#pragma unroll
        for (int t = 0; t < LPP; t++) m = fmaxf(m, 0.25f * lrow[t]);
        float ssum = 0.f;
#pragma unroll
        for (int t = 0; t < LPP; t++) {
            float e = __expf(0.25f * lrow[t] - m);
            lrow[t] = e;
            ssum += e;
        }
        float inv = 1.f / ssum;
#pragma unroll
        for (int t = 0; t < LPP; t++) lrow[t] *= inv;
    }
    __syncthreads();

    // ---- Phase E: weighted sum -> transposed hidden [c][q] ------------------
    for (int i = tid; i < QB * 128; i += THREADS) {
        const int q = i >> 7;
        const int hd = i & 127;
        const int h = hd / D_HEAD;
        const int d = hd % D_HEAD;
        float a = 0.f;
        const float* attn = &sm[SM_LG + q * NSAMP + h * LPP];
        const float* kk = &sm[SM_KS + (q * NSAMP + h * LPP) * D_HEAD + d];
#pragma unroll
        for (int lp = 0; lp < LPP; lp++)
            a += attn[lp] * kk[lp * D_HEAD];
        sm[SM_HT + hd * QB + q] = a;
    }
    __syncthreads();

    // ---- Phase F: output projection out[q][o] = hs[q] . WoutT[:,o] + b -----
    {
        const int o = tid & 127;
        const int half = tid >> 7;   // 0 -> q 0..3, 1 -> q 4..7
        unsigned long long acc[2] = {0, 0};
        const float* wt = WoutT + o;
#pragma unroll 4
        for (int c = 0; c < 128; c++) {
            unsigned long long ww = bcast2(__ldg(wt + c * 128));
            const unsigned long long* hp =
                reinterpret_cast<const unsigned long long*>(&sm[SM_HT + c * QB + half * 4]);
            ffma2(acc[0], ww, hp[0]);
            ffma2(acc[1], ww, hp[1]);
        }
        const float b = __ldg(bout + o);
#pragma unroll
        for (int k = 0; k < 2; k++) {
            const int q = half * 4 + 2 * k;
            out[(qbase + q) * 128 + o]     = lo2(acc[k]) + b;
            out[(qbase + q + 1) * 128 + o] = hi2(acc[k]) + b;
        }
    }
}

// ---------------------------------------------------------------------------
// Launch
// ---------------------------------------------------------------------------
extern "C" void kernel_launch(void* const* d_in, const int* in_sizes, int n_in,
                              void* d_out, int out_size) {
    const float* query = (const float*)d_in[0];
    const float* refp  = (const float*)d_in[1];
    const float* feat0 = (const float*)d_in[2];
    const float* feat1 = (const float*)d_in[3];
    const float* feat2 = (const float*)d_in[4];
    const float* Woff  = (const float*)d_in[6];
    const float* boff  = (const float*)d_in[7];
    const float* Wk0   = (const float*)d_in[8];
    const float* bk0   = (const float*)d_in[9];
    const float* Wk1   = (const float*)d_in[10];
    const float* bk1   = (const float*)d_in[11];
    const float* Wk2   = (const float*)d_in[12];
    const float* bk2   = (const float*)d_in[13];
    const float* Wout  = (const float*)d_in[14];
    const float* bout  = (const float*)d_in[15];
    float* out = (float*)d_out;

    float *wofft, *woutt;
    cudaGetSymbolAddress((void**)&wofft, g_wofft);
    cudaGetSymbolAddress((void**)&woutt, g_woutt);

    prep_kernel<<<712, 128>>>(feat0, feat1, feat2, Wk0, Wk1, Wk2, Woff, Wout);

    static bool attr_set = false;
    if (!attr_set) {
        cudaFuncSetAttribute(msda_main_kernel,
                             cudaFuncAttributeMaxDynamicSharedMemorySize,
                             (int)SMEM_BYTES);
        attr_set = true;
    }
    msda_main_kernel<<<LQ / QB, THREADS, SMEM_BYTES>>>(
        query, refp, wofft, boff, bk0, bk1, bk2, woutt, bout, out);
}

// round 4
// speedup vs baseline: 2.2962x; 1.1498x over previous
#include <cuda_runtime.h>
#include <math.h>

#define N_HEADS   8
#define N_LEVELS  3
#define N_POINTS  4
#define D_MODEL   128
#define D_HEAD    16
#define LQ        6400

#define H0 128
#define W0 128
#define H1 64
#define W1 64
#define H2 32
#define W2 32
#define HW0 (H0*W0)
#define HW1 (H1*W1)
#define HW2 (H2*W2)

// scratch
__device__ float g_proj0[HW0 * 128];
__device__ float g_proj1[HW1 * 128];
__device__ float g_proj2[HW2 * 128];
__device__ float g_wofft[128 * 192];   // WoffT[c][j]
__device__ float g_woutt[128 * 128];   // WoutT[c][o]
__device__ float g_loc[LQ * 192];      // final sampling locations per (q, j)

typedef unsigned long long ull;

// ---------------------------------------------------------------------------
// packed f32x2 helpers
// ---------------------------------------------------------------------------
__device__ __forceinline__ void ffma2(ull& acc, ull a, ull b) {
    asm("fma.rn.f32x2 %0, %1, %2, %0;" : "+l"(acc) : "l"(a), "l"(b));
}
__device__ __forceinline__ ull bcast2(float w) {
    unsigned int wb = __float_as_uint(w);
    return ((ull)wb << 32) | wb;
}
__device__ __forceinline__ float lo2(ull v) { return __uint_as_float((unsigned int)v); }
__device__ __forceinline__ float hi2(ull v) { return __uint_as_float((unsigned int)(v >> 32)); }

// ---------------------------------------------------------------------------
// prep building blocks (128 threads each)
// ---------------------------------------------------------------------------
template <int C>
__device__ void proj_block(const float* __restrict__ feat,
                           const float* __restrict__ Wk,
                           float* __restrict__ out, int HW, int blk,
                           float* s) {
    constexpr int PIX = 32;
    const int base = blk * PIX;
    const int tid = threadIdx.x;

    for (int i = tid; i < C * PIX; i += 128) {
        int c = i >> 5, px = i & 31;
        s[i] = feat[c * HW + base + px];
    }
    __syncthreads();

    ull acc[PIX / 2];
#pragma unroll
    for (int v = 0; v < PIX / 2; v++) acc[v] = 0ULL;

    const float4* wrow4 = reinterpret_cast<const float4*>(Wk + tid * C);
#pragma unroll 2
    for (int c4 = 0; c4 < C / 4; c4++) {
        float4 w4 = __ldg(wrow4 + c4);
        float wv[4] = {w4.x, w4.y, w4.z, w4.w};
#pragma unroll
        for (int u = 0; u < 4; u++) {
            ull ww = bcast2(wv[u]);
            const ull* s2 = reinterpret_cast<const ull*>(&s[(c4 * 4 + u) * PIX]);
#pragma unroll
            for (int v = 0; v < PIX / 2; v++)
                ffma2(acc[v], ww, s2[v]);
        }
    }
#pragma unroll
    for (int v = 0; v < PIX / 2; v++) {
        out[(base + 2 * v) * 128 + tid]     = lo2(acc[v]);
        out[(base + 2 * v + 1) * 128 + tid] = hi2(acc[v]);
    }
}

__device__ void transpose_block(int b,
                                const float* __restrict__ Woff,
                                const float* __restrict__ Wout,
                                float* __restrict__ WoffT,
                                float* __restrict__ WoutT,
                                float* tile) {
    const float* in;
    float* out;
    int rows, cols, bx, by;
    if (b < 24) {
        in = Woff; out = WoffT; rows = 192; cols = 128;
        by = (b / 4) * 32; bx = (b % 4) * 32;
    } else {
        b -= 24;
        in = Wout; out = WoutT; rows = 128; cols = 128;
        by = (b / 4) * 32; bx = (b % 4) * 32;
    }
    const int tx = threadIdx.x & 31;
    const int ty0 = threadIdx.x >> 5;
    const int x = bx + tx;
#pragma unroll
    for (int dy = ty0; dy < 32; dy += 4) {
        int y = by + dy;
        if (y < rows && x < cols) tile[dy * 33 + tx] = in[y * cols + x];
    }
    __syncthreads();
    const int xo = by + tx;
#pragma unroll
    for (int dy = ty0; dy < 32; dy += 4) {
        int yo = bx + dy;
        if (yo < cols && xo < rows) out[yo * rows + xo] = tile[tx * 33 + dy];
    }
}

// location block: 16 queries; loc[q][j] = ref[q][l][xy] + (q . WoffT[:,j] + boff[j]) / dim_l
__device__ void loc_block(int b,
                          const float* __restrict__ query,
                          const float* __restrict__ refp,
                          const float* __restrict__ WoffT,
                          const float* __restrict__ boff,
                          float* s /* >= 2144 floats */) {
    const int qb = b * 16;
    const int tid = threadIdx.x;
    // s[0..2047]: q tile [c][16] ; s[2048..2143]: ref [16][6]
    for (int i = tid; i < 16 * 128; i += 128) {
        int q = i >> 7, c = i & 127;
        s[c * 16 + q] = query[(qb + q) * 128 + c];
    }
    if (tid < 96) s[2048 + tid] = refp[qb * 6 + tid];
    __syncthreads();

    for (int j = tid; j < 192; j += 128) {
        const int xy = j & 1;
        const int l = (j >> 3) % 3;
        const float scale = 1.f / (float)(128 >> l);

        ull acc[8];
#pragma unroll
        for (int k = 0; k < 8; k++) acc[k] = 0ULL;

        const float* wcol = WoffT + j;
#pragma unroll 4
        for (int c = 0; c < 128; c++) {
            ull w = bcast2(__ldg(wcol + c * 192));
            const ull* s2 = reinterpret_cast<const ull*>(&s[c * 16]);
#pragma unroll
            for (int k = 0; k < 8; k++)
                ffma2(acc[k], w, s2[k]);
        }
        const float bo = __ldg(boff + j);
#pragma unroll
        for (int k = 0; k < 8; k++) {
            const int q0 = 2 * k, q1 = 2 * k + 1;
            const float r0 = s[2048 + q0 * 6 + l * 2 + xy];
            const float r1 = s[2048 + q1 * 6 + l * 2 + xy];
            g_loc[(qb + q0) * 192 + j] = r0 + (lo2(acc[k]) + bo) * scale;
            g_loc[(qb + q1) * 192 + j] = r1 + (hi2(acc[k]) + bo) * scale;
        }
    }
}

// prep: 512 proj0 + 128 proj1 + 32 proj2 + 40 transpose + 400 loc = 1112 blocks
__global__ __launch_bounds__(128)
void prep_kernel(const float* __restrict__ feat0,
                 const float* __restrict__ feat1,
                 const float* __restrict__ feat2,
                 const float* __restrict__ Wk0,
                 const float* __restrict__ Wk1,
                 const float* __restrict__ Wk2,
                 const float* __restrict__ Woff,
                 const float* __restrict__ Wout,
                 const float* __restrict__ query,
                 const float* __restrict__ refp,
                 const float* __restrict__ boff) {
    __shared__ float s[128 * 32];
    const int b = blockIdx.x;
    if (b < 512) {
        proj_block<128>(feat0, Wk0, g_proj0, HW0, b, s);
    } else if (b < 640) {
        proj_block<128>(feat1, Wk1, g_proj1, HW1, b - 512, s);
    } else if (b < 672) {
        proj_block<64>(feat2, Wk2, g_proj2, HW2, b - 640, s);
    } else if (b < 712) {
        transpose_block(b - 672, Woff, Wout, g_wofft, g_woutt, s);
    } else {
        loc_block(b - 712, query, refp, g_wofft, boff, s);
    }
}

// ---------------------------------------------------------------------------
// Fused attention kernel. QB=4 queries / block, 256 threads.
// ---------------------------------------------------------------------------
#define QB 4
#define THREADS 256
#define NSAMP (N_HEADS * N_LEVELS * N_POINTS)   // 96
#define LPP   (N_LEVELS * N_POINTS)             // 12

// smem (floats): QS 512 | LOC 768 (HT 512 aliases) | KS 6144 (PF 512 aliases) | LG 384
#define SM_QS    0
#define SM_LOC   (SM_QS + QB*128)            // 512
#define SM_HT    SM_LOC                      // alias (LOC dead after phase C)
#define SM_KS    (SM_LOC + QB*192)           // 1280
#define SM_PF    SM_KS                       // alias (KS dead after phase E)
#define SM_LG    (SM_KS + QB*NSAMP*16)       // 7424
#define SM_TOTAL (SM_LG + QB*NSAMP)          // 7808
#define SMEM_BYTES (SM_TOTAL * sizeof(float))

__global__ __launch_bounds__(THREADS)
void msda_main_kernel(const float* __restrict__ query,
                      const float* __restrict__ bk0,
                      const float* __restrict__ bk1,
                      const float* __restrict__ bk2,
                      const float* __restrict__ WoutT,
                      const float* __restrict__ bout,
                      float* __restrict__ out) {
    extern __shared__ float sm[];
    const int tid = threadIdx.x;
    const int qbase = blockIdx.x * QB;

    // ---- Phase A: queries + precomputed locations --------------------------
    for (int i = tid; i < QB * 128; i += THREADS)
        sm[SM_QS + i] = query[qbase * 128 + i];
    for (int i = tid; i < QB * 192; i += THREADS)
        sm[SM_LOC + i] = g_loc[qbase * 192 + i];
    __syncthreads();

    // ---- Phase C: quad-cooperative bilinear gather + logits ----------------
    // i = q*384 + s*4 + d4 ; 1536 tasks, 6 iterations.
#pragma unroll
    for (int it = 0; it < 6; it++) {
        const int i = it * THREADS + tid;
        const int q = i / 384;
        const int r = i - q * 384;
        const int s = r >> 2;
        const int d4 = r & 3;
        const int h = s / LPP;
        const int lp = s - h * LPP;
        const int l = lp >> 2;

        const float* proj;
        const float* bk;
        int Wl, Hl;
        if (l == 0)      { proj = g_proj0; bk = bk0; Wl = W0; Hl = H0; }
        else if (l == 1) { proj = g_proj1; bk = bk1; Wl = W1; Hl = H1; }
        else             { proj = g_proj2; bk = bk2; Wl = W2; Hl = H2; }

        const float locx = sm[SM_LOC + q * 192 + s * 2];
        const float locy = sm[SM_LOC + q * 192 + s * 2 + 1];

        const float x = locx * (float)Wl - 0.5f;
        const float y = locy * (float)Hl - 0.5f;
        const float xf = floorf(x), yf = floorf(y);
        const int x0 = (int)xf, y0 = (int)yf;
        const float wx = x - xf, wy = y - yf;

        const int coff = h * D_HEAD + d4 * 4;
        const float* projc = proj + coff;

        float wgt[4];
        const float4* addr[4];
#pragma unroll
        for (int t = 0; t < 4; t++) {
            const int xi = x0 + (t & 1);
            const int yi = y0 + (t >> 1);
            const bool valid = (xi >= 0) & (xi < Wl) & (yi >= 0) & (yi < Hl);
            const float w = ((t & 1) ? wx : (1.f - wx)) * ((t >> 1) ? wy : (1.f - wy));
            wgt[t] = valid ? w : 0.f;
            const int xic = min(max(xi, 0), Wl - 1);
            const int yic = min(max(yi, 0), Hl - 1);
            addr[t] = reinterpret_cast<const float4*>(projc + (yic * Wl + xic) * 128);
        }
        float4 v0 = __ldg(addr[0]);
        float4 v1 = __ldg(addr[1]);
        float4 v2 = __ldg(addr[2]);
        float4 v3 = __ldg(addr[3]);
        float4 bb = __ldg(reinterpret_cast<const float4*>(bk + coff));

        float4 k;
        k.x = bb.x + wgt[0] * v0.x + wgt[1] * v1.x + wgt[2] * v2.x + wgt[3] * v3.x;
        k.y = bb.y + wgt[0] * v0.y + wgt[1] * v1.y + wgt[2] * v2.y + wgt[3] * v3.y;
        k.z = bb.z + wgt[0] * v0.z + wgt[1] * v1.z + wgt[2] * v2.z + wgt[3] * v3.z;
        k.w = bb.w + wgt[0] * v0.w + wgt[1] * v1.w + wgt[2] * v2.w + wgt[3] * v3.w;

        const float4 qv = *reinterpret_cast<const float4*>(&sm[SM_QS + q * 128 + coff]);
        float part = qv.x * k.x + qv.y * k.y + qv.z * k.z + qv.w * k.w;
        part += __shfl_xor_sync(0xffffffffu, part, 1);
        part += __shfl_xor_sync(0xffffffffu, part, 2);

        *reinterpret_cast<float4*>(&sm[SM_KS + (q * NSAMP + s) * D_HEAD + d4 * 4]) = k;
        if (d4 == 0) sm[SM_LG + q * NSAMP + s] = part;
    }
    __syncthreads();

    // ---- Phase D: softmax per (q, h) over 12 -------------------------------
    if (tid < QB * N_HEADS) {
        const int q = tid / N_HEADS, h = tid % N_HEADS;
        float* lrow = &sm[SM_LG + q * NSAMP + h * LPP];
        float m = -1e30f;
#pragma unroll
        for (int t = 0; t < LPP; t++) m = fmaxf(m, 0.25f * lrow[t]);
        float ssum = 0.f;
#pragma unroll
        for (int t = 0; t < LPP; t++) {
            float e = __expf(0.25f * lrow[t] - m);
            lrow[t] = e;
            ssum += e;
        }
        float inv = 1.f / ssum;
#pragma unroll
        for (int t = 0; t < LPP; t++) lrow[t] *= inv;
    }
    __syncthreads();

    // ---- Phase E: weighted sum -> HT [c][q] (overwrites LOC) ---------------
#pragma unroll
    for (int it = 0; it < 2; it++) {
        const int i = it * THREADS + tid;
        const int q = i >> 7;
        const int hd = i & 127;
        const int h = hd / D_HEAD;
        const int d = hd % D_HEAD;
        float a = 0.f;
        const float* attn = &sm[SM_LG + q * NSAMP + h * LPP];
        const float* kk = &sm[SM_KS + (q * NSAMP + h * LPP) * D_HEAD + d];
#pragma unroll
        for (int lp = 0; lp < LPP; lp++)
            a += attn[lp] * kk[lp * D_HEAD];
        sm[SM_HT + hd * QB + q] = a;
    }
    __syncthreads();

    // ---- Phase F: out[q][o] = hs[q] . WoutT[:,o] + b, c-split over 2 halves -
    {
        const int o = tid & 127;
        const int chalf = tid >> 7;
        const int cbase = chalf * 64;
        ull acc[2] = {0, 0};
        const float* wt = WoutT + o;
#pragma unroll 4
        for (int c = 0; c < 64; c++) {
            const int cc = cbase + c;
            ull ww = bcast2(__ldg(wt + cc * 128));
            const ull* hp = reinterpret_cast<const ull*>(&sm[SM_HT + cc * QB]);
            ffma2(acc[0], ww, hp[0]);
            ffma2(acc[1], ww, hp[1]);
        }
        if (chalf == 1) {
            ull* pf = reinterpret_cast<ull*>(&sm[SM_PF]);
            pf[o * 2]     = acc[0];
            pf[o * 2 + 1] = acc[1];
        }
        __syncthreads();
        if (chalf == 0) {
            const float* pf = &sm[SM_PF + o * 4];
            const float b = __ldg(bout + o);
            float r0 = lo2(acc[0]) + pf[0] + b;
            float r1 = hi2(acc[0]) + pf[1] + b;
            float r2 = lo2(acc[1]) + pf[2] + b;
            float r3 = hi2(acc[1]) + pf[3] + b;
            out[(qbase + 0) * 128 + o] = r0;
            out[(qbase + 1) * 128 + o] = r1;
            out[(qbase + 2) * 128 + o] = r2;
            out[(qbase + 3) * 128 + o] = r3;
        }
    }
}

// ---------------------------------------------------------------------------
// Launch
// ---------------------------------------------------------------------------
extern "C" void kernel_launch(void* const* d_in, const int* in_sizes, int n_in,
                              void* d_out, int out_size) {
    const float* query = (const float*)d_in[0];
    const float* refp  = (const float*)d_in[1];
    const float* feat0 = (const float*)d_in[2];
    const float* feat1 = (const float*)d_in[3];
    const float* feat2 = (const float*)d_in[4];
    const float* Woff  = (const float*)d_in[6];
    const float* boff  = (const float*)d_in[7];
    const float* Wk0   = (const float*)d_in[8];
    const float* bk0   = (const float*)d_in[9];
    const float* Wk1   = (const float*)d_in[10];
    const float* bk1   = (const float*)d_in[11];
    const float* Wk2   = (const float*)d_in[12];
    const float* bk2   = (const float*)d_in[13];
    const float* Wout  = (const float*)d_in[14];
    const float* bout  = (const float*)d_in[15];
    float* out = (float*)d_out;

    float *woutt;
    cudaGetSymbolAddress((void**)&woutt, g_woutt);

    prep_kernel<<<1112, 128>>>(feat0, feat1, feat2, Wk0, Wk1, Wk2,
                               Woff, Wout, query, refp, boff);

    static bool attr_set = false;
    if (!attr_set) {
        cudaFuncSetAttribute(msda_main_kernel,
                             cudaFuncAttributeMaxDynamicSharedMemorySize,
                             (int)SMEM_BYTES);
        attr_set = true;
    }
    msda_main_kernel<<<LQ / QB, THREADS, SMEM_BYTES>>>(
        query, bk0, bk1, bk2, woutt, bout, out);
}

// round 5
// speedup vs baseline: 2.4175x; 1.0528x over previous
#include <cuda_runtime.h>
#include <math.h>

#define N_HEADS   8
#define N_LEVELS  3
#define N_POINTS  4
#define D_MODEL   128
#define D_HEAD    16
#define LQ        6400

#define H0 128
#define W0 128
#define H1 64
#define W1 64
#define H2 32
#define W2 32
#define HW0 (H0*W0)
#define HW1 (H1*W1)
#define HW2 (H2*W2)

// scratch
__device__ float g_proj0[HW0 * 128];
__device__ float g_proj1[HW1 * 128];
__device__ float g_proj2[HW2 * 128];
__device__ float g_wofft[128 * 192];   // WoffT[c][j]
__device__ float g_woutt[128 * 128];   // WoutT[c][o]
__device__ float g_wk0t[128 * 128];    // Wk0T[c][o]
__device__ float g_wk1t[128 * 128];
__device__ float g_wk2t[64 * 128];
__device__ float g_loc[LQ * 192];      // final sampling locations per (q, j)
__device__ uint4 g_lut[96];            // per-sample: {ptr_lo, ptr_hi, W|H<<16, h*3+l}

typedef unsigned long long ull;

// ---------------------------------------------------------------------------
// packed f32x2 helpers
// ---------------------------------------------------------------------------
__device__ __forceinline__ void ffma2(ull& acc, ull a, ull b) {
    asm("fma.rn.f32x2 %0, %1, %2, %0;" : "+l"(acc) : "l"(a), "l"(b));
}
__device__ __forceinline__ ull bcast2(float w) {
    unsigned int wb = __float_as_uint(w);
    return ((ull)wb << 32) | wb;
}
__device__ __forceinline__ float lo2(ull v) { return __uint_as_float((unsigned int)v); }
__device__ __forceinline__ float hi2(ull v) { return __uint_as_float((unsigned int)(v >> 32)); }

// ---------------------------------------------------------------------------
// pre_kernel: all 5 weight transposes + sample LUT. 81 blocks x 128 threads.
// blocks [0,24) Woff, [24,40) Wout, [40,56) Wk0, [56,72) Wk1, [72,80) Wk2,
// block 80 builds LUT.
// ---------------------------------------------------------------------------
__global__ __launch_bounds__(128)
void pre_kernel(const float* __restrict__ Woff,
                const float* __restrict__ Wout,
                const float* __restrict__ Wk0,
                const float* __restrict__ Wk1,
                const float* __restrict__ Wk2) {
    __shared__ float tile[32 * 33];
    int b = blockIdx.x;
    if (b == 80) {
        int s = threadIdx.x;
        if (s < 96) {
            int h = s / 12, lp = s % 12, l = lp >> 2;
            const float* base = (l == 0) ? g_proj0 : (l == 1) ? g_proj1 : g_proj2;
            ull p = (ull)(base + h * D_HEAD);
            int Wl = 128 >> l, Hl = 128 >> l;
            g_lut[s] = make_uint4((unsigned)p, (unsigned)(p >> 32),
                                  (unsigned)(Wl | (Hl << 16)), (unsigned)(h * 3 + l));
        }
        return;
    }
    const float* in;
    float* out;
    int rows, cols, t;
    if (b < 24)      { in = Woff; out = g_wofft; rows = 192; cols = 128; t = b; }
    else if (b < 40) { in = Wout; out = g_woutt; rows = 128; cols = 128; t = b - 24; }
    else if (b < 56) { in = Wk0;  out = g_wk0t;  rows = 128; cols = 128; t = b - 40; }
    else if (b < 72) { in = Wk1;  out = g_wk1t;  rows = 128; cols = 128; t = b - 56; }
    else             { in = Wk2;  out = g_wk2t;  rows = 128; cols = 64;  t = b - 72; }
    const int tpr = cols / 32;
    const int by = (t / tpr) * 32, bx = (t % tpr) * 32;
    const int tx = threadIdx.x & 31;
    const int ty0 = threadIdx.x >> 5;
    const int x = bx + tx;
#pragma unroll
    for (int dy = ty0; dy < 32; dy += 4) {
        int y = by + dy;
        if (y < rows && x < cols) tile[dy * 33 + tx] = in[y * cols + x];
    }
    __syncthreads();
    const int xo = by + tx;
#pragma unroll
    for (int dy = ty0; dy < 32; dy += 4) {
        int yo = bx + dy;
        if (yo < cols && xo < rows) out[yo * rows + xo] = tile[tx * 33 + dy];
    }
}

// ---------------------------------------------------------------------------
// prep building blocks (128 threads each)
// ---------------------------------------------------------------------------
template <int C>
__device__ void proj_block(const float* __restrict__ feat,
                           const float* __restrict__ WkT,   // [C][128]
                           float* __restrict__ out, int HW, int blk,
                           float* s) {
    constexpr int PIX = 32;
    const int base = blk * PIX;
    const int tid = threadIdx.x;

    for (int i = tid; i < C * PIX; i += 128) {
        int c = i >> 5, px = i & 31;
        s[i] = feat[c * HW + base + px];
    }
    __syncthreads();

    ull acc[PIX / 2];
#pragma unroll
    for (int v = 0; v < PIX / 2; v++) acc[v] = 0ULL;

    const float* wcol = WkT + tid;   // lanes consecutive -> coalesced
#pragma unroll 4
    for (int c = 0; c < C; c++) {
        ull ww = bcast2(__ldg(wcol + c * 128));
        const ull* s2 = reinterpret_cast<const ull*>(&s[c * PIX]);
#pragma unroll
        for (int v = 0; v < PIX / 2; v++)
            ffma2(acc[v], ww, s2[v]);
    }
#pragma unroll
    for (int v = 0; v < PIX / 2; v++) {
        out[(base + 2 * v) * 128 + tid]     = lo2(acc[v]);
        out[(base + 2 * v + 1) * 128 + tid] = hi2(acc[v]);
    }
}

// location block: 16 queries; balanced 384 (j, qhalf) tasks over 128 threads.
__device__ void loc_block(int b,
                          const float* __restrict__ query,
                          const float* __restrict__ refp,
                          const float* __restrict__ boff,
                          float* s /* >= 2144 floats */) {
    const int qb = b * 16;
    const int tid = threadIdx.x;
    // s[0..2047]: q tile [c][16] ; s[2048..2143]: ref [16][6]
    for (int i = tid; i < 16 * 128; i += 128) {
        int q = i >> 7, c = i & 127;
        s[c * 16 + q] = query[(qb + q) * 128 + c];
    }
    if (tid < 96) s[2048 + tid] = refp[qb * 6 + tid];
    __syncthreads();

#pragma unroll
    for (int k = 0; k < 3; k++) {
        const int t = k * 128 + tid;      // 0..383
        const int j = t % 192;
        const int qh = t / 192;           // 0 or 1 (8 queries each)
        const int xy = j & 1;
        const int l = (j >> 3) % 3;
        const float scale = 1.f / (float)(128 >> l);

        ull acc[4] = {0, 0, 0, 0};
        const float* wcol = g_wofft + j;
#pragma unroll 4
        for (int c = 0; c < 128; c++) {
            ull w = bcast2(__ldg(wcol + c * 192));
            const ull* s2 = reinterpret_cast<const ull*>(&s[c * 16 + qh * 8]);
#pragma unroll
            for (int v = 0; v < 4; v++)
                ffma2(acc[v], w, s2[v]);
        }
        const float bo = __ldg(boff + j);
#pragma unroll
        for (int v = 0; v < 4; v++) {
            const int q0 = qh * 8 + 2 * v, q1 = q0 + 1;
            const float r0 = s[2048 + q0 * 6 + l * 2 + xy];
            const float r1 = s[2048 + q1 * 6 + l * 2 + xy];
            g_loc[(qb + q0) * 192 + j] = r0 + (lo2(acc[v]) + bo) * scale;
            g_loc[(qb + q1) * 192 + j] = r1 + (hi2(acc[v]) + bo) * scale;
        }
    }
}

// prep: 512 proj0 + 128 proj1 + 32 proj2 + 400 loc = 1072 blocks
__global__ __launch_bounds__(128)
void prep_kernel(const float* __restrict__ feat0,
                 const float* __restrict__ feat1,
                 const float* __restrict__ feat2,
                 const float* __restrict__ query,
                 const float* __restrict__ refp,
                 const float* __restrict__ boff) {
    __shared__ float s[128 * 32];
    const int b = blockIdx.x;
    if (b < 400) {
        loc_block(b, query, refp, boff, s);
    } else if (b < 912) {
        proj_block<128>(feat0, g_wk0t, g_proj0, HW0, b - 400, s);
    } else if (b < 1040) {
        proj_block<128>(feat1, g_wk1t, g_proj1, HW1, b - 912, s);
    } else {
        proj_block<64>(feat2, g_wk2t, g_proj2, HW2, b - 1040, s);
    }
}

// ---------------------------------------------------------------------------
// Fused attention kernel. QB=4 queries / block, 256 threads.
// ---------------------------------------------------------------------------
#define QB 4
#define THREADS 256
#define NSAMP (N_HEADS * N_LEVELS * N_POINTS)   // 96
#define LPP   (N_LEVELS * N_POINTS)             // 12

#define SM_QS    0
#define SM_LOC   (SM_QS + QB*128)            // 512
#define SM_HT    SM_LOC                      // alias (LOC dead after C)
#define SM_KS    (SM_LOC + QB*192)           // 1280
#define SM_PF    SM_KS                       // alias (KS dead after E)
#define SM_LG    (SM_KS + QB*NSAMP*16)       // 7424
#define SM_QBK   (SM_LG + QB*NSAMP)          // 7808  [q][h][l] 96
#define SM_TOTAL (SM_QBK + QB*24)            // 7904
#define SMEM_BYTES (SM_TOTAL * sizeof(float))

__global__ __launch_bounds__(THREADS)
void msda_main_kernel(const float* __restrict__ query,
                      const float* __restrict__ bk0,
                      const float* __restrict__ bk1,
                      const float* __restrict__ bk2,
                      const float* __restrict__ WoutT,
                      const float* __restrict__ bout,
                      float* __restrict__ out) {
    extern __shared__ float sm[];
    const int tid = threadIdx.x;
    const int qbase = blockIdx.x * QB;

    // ---- Phase A: queries + precomputed locations --------------------------
    for (int i = tid; i < QB * 128; i += THREADS)
        sm[SM_QS + i] = query[qbase * 128 + i];
    for (int i = tid; i < QB * 192; i += THREADS)
        sm[SM_LOC + i] = g_loc[qbase * 192 + i];
    __syncthreads();

    // ---- Phase A2: qbk[q][h][l] = q_h . bk_l_h ------------------------------
    if (tid < QB * 24) {
        const int q = tid / 24;
        const int r = tid % 24;
        const int h = r / 3;
        const int l = r % 3;
        const float* bk = (l == 0) ? bk0 : (l == 1) ? bk1 : bk2;
        const float* qp = &sm[SM_QS + q * 128 + h * D_HEAD];
        float a = 0.f;
#pragma unroll
        for (int d = 0; d < D_HEAD; d++)
            a += qp[d] * __ldg(bk + h * D_HEAD + d);
        sm[SM_QBK + tid] = a;
    }
    __syncthreads();

    // ---- Phase C: quad-cooperative bilinear gather + logits ----------------
#pragma unroll
    for (int it = 0; it < 6; it++) {
        const int i = it * THREADS + tid;
        const int q = i / 384;
        const int r = i - q * 384;
        const int s = r >> 2;
        const int d4 = r & 3;

        const uint4 e = __ldg(&g_lut[s]);
        const float* projc = (const float*)(((ull)e.y << 32) | (ull)e.x);
        const int Wl = (int)(e.z & 0xffffu);
        const int Hl = (int)(e.z >> 16);

        const float locx = sm[SM_LOC + q * 192 + s * 2];
        const float locy = sm[SM_LOC + q * 192 + s * 2 + 1];

        const float x = locx * (float)Wl - 0.5f;
        const float y = locy * (float)Hl - 0.5f;
        const float xf = floorf(x), yf = floorf(y);
        const int x0 = (int)xf, y0 = (int)yf;
        const float wx = x - xf, wy = y - yf;

        float wgt[4];
        const float4* addr[4];
#pragma unroll
        for (int t = 0; t < 4; t++) {
            const int xi = x0 + (t & 1);
            const int yi = y0 + (t >> 1);
            const bool valid = (xi >= 0) & (xi < Wl) & (yi >= 0) & (yi < Hl);
            const float w = ((t & 1) ? wx : (1.f - wx)) * ((t >> 1) ? wy : (1.f - wy));
            wgt[t] = valid ? w : 0.f;
            const int xic = min(max(xi, 0), Wl - 1);
            const int yic = min(max(yi, 0), Hl - 1);
            addr[t] = reinterpret_cast<const float4*>(projc + (yic * Wl + xic) * 128) + d4;
        }
        float4 v0 = __ldg(addr[0]);
        float4 v1 = __ldg(addr[1]);
        float4 v2 = __ldg(addr[2]);
        float4 v3 = __ldg(addr[3]);

        float4 k;
        k.x = wgt[0] * v0.x + wgt[1] * v1.x + wgt[2] * v2.x + wgt[3] * v3.x;
        k.y = wgt[0] * v0.y + wgt[1] * v1.y + wgt[2] * v2.y + wgt[3] * v3.y;
        k.z = wgt[0] * v0.z + wgt[1] * v1.z + wgt[2] * v2.z + wgt[3] * v3.z;
        k.w = wgt[0] * v0.w + wgt[1] * v1.w + wgt[2] * v2.w + wgt[3] * v3.w;

        const int coff = (s / LPP) * D_HEAD + d4 * 4;   // h*16 + d4*4
        const float4 qv = *reinterpret_cast<const float4*>(&sm[SM_QS + q * 128 + coff]);
        float part = qv.x * k.x + qv.y * k.y + qv.z * k.z + qv.w * k.w;
        part += __shfl_xor_sync(0xffffffffu, part, 1);
        part += __shfl_xor_sync(0xffffffffu, part, 2);

        *reinterpret_cast<float4*>(&sm[SM_KS + (q * NSAMP + s) * D_HEAD + d4 * 4]) = k;
        if (d4 == 0)
            sm[SM_LG + q * NSAMP + s] = part + sm[SM_QBK + q * 24 + e.w];
    }
    __syncthreads();

    // ---- Phase D: softmax per (q, h) over 12 -------------------------------
    if (tid < QB * N_HEADS) {
        const int q = tid / N_HEADS, h = tid % N_HEADS;
        float* lrow = &sm[SM_LG + q * NSAMP + h * LPP];
        float m = -1e30f;
#pragma unroll
        for (int t = 0; t < LPP; t++) m = fmaxf(m, 0.25f * lrow[t]);
        float ssum = 0.f;
#pragma unroll
        for (int t = 0; t < LPP; t++) {
            float e = __expf(0.25f * lrow[t] - m);
            lrow[t] = e;
            ssum += e;
        }
        float inv = 1.f / ssum;
#pragma unroll
        for (int t = 0; t < LPP; t++) lrow[t] *= inv;
    }
    __syncthreads();

    // ---- Phase E: weighted sum (+ bias via attn level-sums) -> HT [c][q] ---
#pragma unroll
    for (int it = 0; it < 2; it++) {
        const int i = it * THREADS + tid;
        const int q = i >> 7;
        const int hd = i & 127;
        const int h = hd >> 4;
        const int d = hd & 15;
        const float* attn = &sm[SM_LG + q * NSAMP + h * LPP];
        const float* kk = &sm[SM_KS + (q * NSAMP + h * LPP) * D_HEAD + d];
        float a = 0.f;
        float w0 = 0.f, w1 = 0.f, w2 = 0.f;
#pragma unroll
        for (int lp = 0; lp < LPP; lp++) {
            const float at = attn[lp];
            a += at * kk[lp * D_HEAD];
            if (lp < 4) w0 += at;
            else if (lp < 8) w1 += at;
            else w2 += at;
        }
        a += w0 * __ldg(bk0 + hd) + w1 * __ldg(bk1 + hd) + w2 * __ldg(bk2 + hd);
        sm[SM_HT + hd * QB + q] = a;
    }
    __syncthreads();

    // ---- Phase F: out[q][o] = hs[q] . WoutT[:,o] + b, c-split over 2 halves -
    {
        const int o = tid & 127;
        const int chalf = tid >> 7;
        const int cbase = chalf * 64;
        ull acc[2] = {0, 0};
        const float* wt = WoutT + o;
#pragma unroll 4
        for (int c = 0; c < 64; c++) {
            const int cc = cbase + c;
            ull ww = bcast2(__ldg(wt + cc * 128));
            const ull* hp = reinterpret_cast<const ull*>(&sm[SM_HT + cc * QB]);
            ffma2(acc[0], ww, hp[0]);
            ffma2(acc[1], ww, hp[1]);
        }
        if (chalf == 1) {
            ull* pf = reinterpret_cast<ull*>(&sm[SM_PF]);
            pf[o * 2]     = acc[0];
            pf[o * 2 + 1] = acc[1];
        }
        __syncthreads();
        if (chalf == 0) {
            const float* pf = &sm[SM_PF + o * 4];
            const float b = __ldg(bout + o);
            out[(qbase + 0) * 128 + o] = lo2(acc[0]) + pf[0] + b;
            out[(qbase + 1) * 128 + o] = hi2(acc[0]) + pf[1] + b;
            out[(qbase + 2) * 128 + o] = lo2(acc[1]) + pf[2] + b;
            out[(qbase + 3) * 128 + o] = hi2(acc[1]) + pf[3] + b;
        }
    }
}

// ---------------------------------------------------------------------------
// Launch
// ---------------------------------------------------------------------------
extern "C" void kernel_launch(void* const* d_in, const int* in_sizes, int n_in,
                              void* d_out, int out_size) {
    const float* query = (const float*)d_in[0];
    const float* refp  = (const float*)d_in[1];
    const float* feat0 = (const float*)d_in[2];
    const float* feat1 = (const float*)d_in[3];
    const float* feat2 = (const float*)d_in[4];
    const float* Woff  = (const float*)d_in[6];
    const float* boff  = (const float*)d_in[7];
    const float* Wk0   = (const float*)d_in[8];
    const float* bk0   = (const float*)d_in[9];
    const float* Wk1   = (const float*)d_in[10];
    const float* bk1   = (const float*)d_in[11];
    const float* Wk2   = (const float*)d_in[12];
    const float* bk2   = (const float*)d_in[13];
    const float* Wout  = (const float*)d_in[14];
    const float* bout  = (const float*)d_in[15];
    float* out = (float*)d_out;

    float* woutt;
    cudaGetSymbolAddress((void**)&woutt, g_woutt);

    pre_kernel<<<81, 128>>>(Woff, Wout, Wk0, Wk1, Wk2);
    prep_kernel<<<1072, 128>>>(feat0, feat1, feat2, query, refp, boff);

    static bool attr_set = false;
    if (!attr_set) {
        cudaFuncSetAttribute(msda_main_kernel,
                             cudaFuncAttributeMaxDynamicSharedMemorySize,
                             (int)SMEM_BYTES);
        attr_set = true;
    }
    msda_main_kernel<<<LQ / QB, THREADS, SMEM_BYTES>>>(
        query, bk0, bk1, bk2, woutt, bout, out);
}